// round 4
// baseline (speedup 1.0000x reference)
#include <cuda_runtime.h>
#include <cuda_bf16.h>

// ---------------- problem constants ----------------
#define SQ   256
#define BB   8
#define VV   32000
#define EE   300
#define HH   512
#define ERD  64
#define XDIM (EE + ERD)     // 364
#define XH   (XDIM + HH)    // 876
#define MM   (SQ * BB)      // 2048

#define LSTM_BLOCKS 128
#define HPB 4               // h indices per LSTM block
#define KCH 55              // k chunk per lane-column (16*55 = 880 >= 876)

#define CAND_MAX 64
#define CAND_EPS 5e-4f

// ---------------- scratch (device globals; no allocs allowed) ----------------
__device__ float g_xseq[MM * XDIM];            // ~2.98 MB
__device__ float g_hs[MM * HH];                // 4 MB
__device__ float g_logits[(size_t)MM * VV];    // 262 MB (bss, not in cubin)
__device__ unsigned long long g_best[MM];      // packed (ordered-logit, ~v)
__device__ float g_Z[MM];
__device__ int   g_candv[MM * CAND_MAX];
__device__ int   g_candn[MM];
__device__ int   g_vstar[MM];
__device__ unsigned g_bars[SQ];                // per-step grid barrier slots

// ---------------- helpers ----------------
__device__ __forceinline__ void ffma2(unsigned long long &d, unsigned long long a,
                                      unsigned long long b) {
    asm("fma.rn.f32x2 %0, %1, %2, %0;" : "+l"(d) : "l"(a), "l"(b));
}
__device__ __forceinline__ unsigned long long dup2(float f) {
    unsigned long long d;
    asm("mov.b64 %0, {%1, %1};" : "=l"(d) : "f"(f));
    return d;
}
__device__ __forceinline__ float2 unpack2(unsigned long long a) {
    float2 f;
    asm("mov.b64 {%0, %1}, %2;" : "=f"(f.x), "=f"(f.y) : "l"(a));
    return f;
}
__device__ __forceinline__ unsigned long long make_key(float logit, int v) {
    unsigned u = __float_as_uint(logit);
    u = (u & 0x80000000u) ? ~u : (u | 0x80000000u);   // monotone float->uint
    return ((unsigned long long)u << 32) | (unsigned)(0xFFFFFFFFu - (unsigned)v);
}
__device__ __forceinline__ float key_to_float(unsigned long long key) {
    unsigned u = (unsigned)(key >> 32);
    unsigned fb = (u & 0x80000000u) ? (u ^ 0x80000000u) : ~u;
    return __uint_as_float(fb);
}

// ---------------- kernel 0: zero state ----------------
__global__ void k_zero() {
    int t = blockIdx.x * blockDim.x + threadIdx.x;
    if (t < MM) { g_best[t] = 0ull; g_candn[t] = 0; }
    if (t < SQ) g_bars[t] = 0u;
}

// ---------------- kernel 1: build x_seq = [rel_emb | word_in] ----------------
__global__ void k_xseq(const int* __restrict__ tokens, const int* __restrict__ relations,
                       const float* __restrict__ embed, const float* __restrict__ rel_emb) {
    int sb = blockIdx.x;           // s*8 + b
    int s = sb >> 3, b = sb & 7;
    int k = threadIdx.x;
    if (k >= XDIM) return;
    float val;
    if (k < ERD) {
        int r = relations[s * BB + b];
        val = rel_emb[r * ERD + k];
    } else {
        int tok = (s == 0) ? 0 : tokens[(s - 1) * BB + b];
        val = embed[tok * EE + (k - ERD)];
    }
    g_xseq[sb * XDIM + k] = val;
}

// ---------------- kernel 2: persistent LSTM (weights resident in SMEM) ------
__global__ __launch_bounds__(256, 1) void k_lstm(
    const float* __restrict__ hiddens,
    const float* __restrict__ W_ih, const float* __restrict__ W_hh,
    const float* __restrict__ b_ih, const float* __restrict__ b_hh) {
    extern __shared__ float sm[];
    float* w_s    = sm;                       // 16 * 880
    float* xh_s   = w_s + 16 * 880;           // 880 * 8   (index k*8 + b)
    float* part_s = xh_s + 880 * 8;           // 16 * 16 * 8
    float* gate_s = part_s + 16 * 16 * 8;     // 16 * 8
    float* c_s    = gate_s + 16 * 8;          // 4 * 8
    float* bias_s = c_s + 4 * 8;              // 16

    const int tid = threadIdx.x;
    const int j0 = blockIdx.x * HPB;

    for (int idx = tid; idx < 16 * XH; idx += 256) {
        int r = idx / XH, k = idx - r * XH;
        int g = r >> 2, jj = r & 3;
        int row = g * HH + j0 + jj;
        float v = (k < XDIM) ? W_ih[row * XDIM + k] : W_hh[row * HH + (k - XDIM)];
        w_s[r * 880 + k] = v;
    }
    if (tid < 16) {
        int g = tid >> 2, jj = tid & 3;
        int row = g * HH + j0 + jj;
        bias_s[tid] = b_ih[row] + b_hh[row];
    }
    if (tid < 32) {   // c0 = hiddens
        int jj = tid >> 3, b = tid & 7;
        c_s[jj * 8 + b] = hiddens[b * HH + j0 + jj];
    }
    __syncthreads();

    const int r = tid >> 4;
    const int c = tid & 15;
    const int kbeg = c * KCH;
    const int kend = (kbeg + KCH < XH) ? (kbeg + KCH) : XH;
    const float* wrow = w_s + r * 880;

    for (int s = 0; s < SQ; ++s) {
        for (int idx = tid; idx < XH * BB; idx += 256) {
            int k = idx >> 3, b = idx & 7;
            float v;
            if (k < XDIM) {
                v = g_xseq[(s * BB + b) * XDIM + k];
            } else {
                int hk = k - XDIM;
                v = (s == 0) ? hiddens[b * HH + hk]
                             : __ldcg(&g_hs[((s - 1) * BB + b) * HH + hk]);
            }
            xh_s[k * 8 + b] = v;
        }
        __syncthreads();

        unsigned long long a0 = 0ull, a1 = 0ull, a2 = 0ull, a3 = 0ull;
        #pragma unroll 5
        for (int k = kbeg; k < kend; ++k) {
            unsigned long long ww = dup2(wrow[k]);
            const ulonglong2* xp = (const ulonglong2*)(xh_s + k * 8);
            ulonglong2 x01 = xp[0];
            ulonglong2 x23 = xp[1];
            ffma2(a0, x01.x, ww);
            ffma2(a1, x01.y, ww);
            ffma2(a2, x23.x, ww);
            ffma2(a3, x23.y, ww);
        }
        unsigned long long* pp = (unsigned long long*)(part_s + (r * 16 + c) * 8);
        pp[0] = a0; pp[1] = a1; pp[2] = a2; pp[3] = a3;
        __syncthreads();

        if (tid < 128) {
            int rr2 = tid >> 3, b = tid & 7;
            float acc = bias_s[rr2];
            #pragma unroll
            for (int cc = 0; cc < 16; ++cc) acc += part_s[(rr2 * 16 + cc) * 8 + b];
            gate_s[rr2 * 8 + b] = acc;
        }
        __syncthreads();

        if (tid < 32) {    // LSTM cell update, double-precision nonlinearity
            int jj = tid >> 3, b = tid & 7;
            double gi = (double)gate_s[(0 * 4 + jj) * 8 + b];
            double gf = (double)gate_s[(1 * 4 + jj) * 8 + b];
            double gg = (double)gate_s[(2 * 4 + jj) * 8 + b];
            double go = (double)gate_s[(3 * 4 + jj) * 8 + b];
            double cold = (double)c_s[jj * 8 + b];
            double si = 1.0 / (1.0 + exp(-gi));
            double sf = 1.0 / (1.0 + exp(-gf));
            double so = 1.0 / (1.0 + exp(-go));
            double cn = sf * cold + si * tanh(gg);
            float cnf = (float)cn;
            float hnf = (float)(so * tanh((double)cnf));
            c_s[jj * 8 + b] = cnf;
            g_hs[(s * BB + b) * HH + j0 + jj] = hnf;
        }
        __syncthreads();

        if (s != SQ - 1) {   // grid barrier
            if (tid == 0) {
                __threadfence();
                unsigned arr = atomicAdd(&g_bars[s], 1u) + 1u;
                if (arr < (unsigned)LSTM_BLOCKS) {
                    while (*((volatile unsigned*)&g_bars[s]) < (unsigned)LSTM_BLOCKS) { }
                }
            }
            __syncthreads();
        }
    }
}

// ---------------- kernel 3: fp32 logits GEMM, store logits + fp32 argmax ----
#define BM 64
#define BV 64
#define BK 16
__global__ __launch_bounds__(256) void k_logits(const float* __restrict__ Wout,
                                                const float* __restrict__ bout) {
    __shared__ float sA[BK * BM];
    __shared__ unsigned long long sB[BK * BV];
    __shared__ unsigned long long sRed[BM][16];

    const int v0 = blockIdx.x * BV;
    const int m0 = blockIdx.y * BM;
    const int tid = threadIdx.x;

    const int la_m = tid >> 2;
    const int la_k = (tid & 3) << 2;
    const float* Aptr = g_hs + (m0 + la_m) * HH + la_k;
    const float* Bptr = Wout + (size_t)(v0 + la_m) * HH + la_k;

    const int mt = tid >> 4;
    const int vt = tid & 15;

    unsigned long long acc[2][4];
    #pragma unroll
    for (int p = 0; p < 2; ++p)
        #pragma unroll
        for (int j = 0; j < 4; ++j) acc[p][j] = 0ull;

    float4 pa = *(const float4*)Aptr;
    float4 pb = *(const float4*)Bptr;

    const int NT = HH / BK;
    for (int t = 0; t < NT; ++t) {
        sA[(la_k + 0) * BM + la_m] = pa.x;
        sA[(la_k + 1) * BM + la_m] = pa.y;
        sA[(la_k + 2) * BM + la_m] = pa.z;
        sA[(la_k + 3) * BM + la_m] = pa.w;
        sB[(la_k + 0) * BV + la_m] = dup2(pb.x);
        sB[(la_k + 1) * BV + la_m] = dup2(pb.y);
        sB[(la_k + 2) * BV + la_m] = dup2(pb.z);
        sB[(la_k + 3) * BV + la_m] = dup2(pb.w);
        __syncthreads();
        if (t + 1 < NT) {
            pa = *(const float4*)(Aptr + (t + 1) * BK);
            pb = *(const float4*)(Bptr + (t + 1) * BK);
        }
        #pragma unroll
        for (int k = 0; k < BK; ++k) {
            ulonglong2 av = *(const ulonglong2*)(sA + k * BM + mt * 4);
            ulonglong2 w0 = *(const ulonglong2*)(sB + k * BV + vt * 4);
            ulonglong2 w1 = *(const ulonglong2*)(sB + k * BV + vt * 4 + 2);
            ffma2(acc[0][0], av.x, w0.x);
            ffma2(acc[0][1], av.x, w0.y);
            ffma2(acc[0][2], av.x, w1.x);
            ffma2(acc[0][3], av.x, w1.y);
            ffma2(acc[1][0], av.y, w0.x);
            ffma2(acc[1][1], av.y, w0.y);
            ffma2(acc[1][2], av.y, w1.x);
            ffma2(acc[1][3], av.y, w1.y);
        }
        __syncthreads();
    }

    float bvals[4];
    #pragma unroll
    for (int j = 0; j < 4; ++j) bvals[j] = __ldg(&bout[v0 + vt * 4 + j]);

    #pragma unroll
    for (int p = 0; p < 2; ++p) {
        #pragma unroll
        for (int half = 0; half < 2; ++half) {
            int m = mt * 4 + p * 2 + half;
            unsigned long long best = 0ull;
            float4 lg;
            float lv[4];
            #pragma unroll
            for (int j = 0; j < 4; ++j) {
                float2 f = unpack2(acc[p][j]);
                lv[j] = (half == 0 ? f.x : f.y) + bvals[j];
                unsigned long long key = make_key(lv[j], v0 + vt * 4 + j);
                if (key > best) best = key;
            }
            lg.x = lv[0]; lg.y = lv[1]; lg.z = lv[2]; lg.w = lv[3];
            *(float4*)(g_logits + (size_t)(m0 + m) * VV + v0 + vt * 4) = lg;
            sRed[m][vt] = best;
        }
    }
    __syncthreads();
    if (tid < BM) {
        unsigned long long b = sRed[tid][0];
        #pragma unroll
        for (int cc = 1; cc < 16; ++cc)
            if (sRed[tid][cc] > b) b = sRed[tid][cc];
        atomicMax(&g_best[m0 + tid], b);
    }
}

// ---------------- kernel 3b: per-row Z + candidate collection ----------------
__global__ __launch_bounds__(256) void k_scan() {
    const int row = blockIdx.x;
    const int tid = threadIdx.x;
    __shared__ float sSum[256];
    __shared__ int sCnt;
    if (tid == 0) sCnt = 0;
    __syncthreads();

    const float rowmax = key_to_float(g_best[row]);
    const float th = rowmax - CAND_EPS;
    const float* lrow = g_logits + (size_t)row * VV;

    float acc = 0.0f;
    for (int v = tid; v < VV; v += 256) {
        float l = lrow[v];
        acc += expf(l - rowmax);
        if (l >= th) {
            int idx = atomicAdd(&sCnt, 1);
            if (idx < CAND_MAX) g_candv[row * CAND_MAX + idx] = v;
        }
    }
    sSum[tid] = acc;
    __syncthreads();
    for (int st = 128; st > 0; st >>= 1) {
        if (tid < st) sSum[tid] += sSum[tid + st];
        __syncthreads();
    }
    if (tid == 0) {
        g_Z[row] = sSum[0];
        g_candn[row] = (sCnt < CAND_MAX) ? sCnt : CAND_MAX;
    }
}

// ---------------- kernel 3c: fp64 rescore + softmax-quantized argmax ---------
__global__ __launch_bounds__(256) void k_rescore(const float* __restrict__ Wout,
                                                 const float* __restrict__ bout) {
    const int row = blockIdx.x;
    const int tid = threadIdx.x;
    const int warp = tid >> 5, lane = tid & 31;
    __shared__ double sL[CAND_MAX];

    const int n = g_candn[row];
    const float* hrow = g_hs + (size_t)row * HH;

    for (int ci = warp; ci < n; ci += 8) {
        int v = g_candv[row * CAND_MAX + ci];
        const float* wrow = Wout + (size_t)v * HH;
        double d = 0.0;
        #pragma unroll
        for (int k = lane; k < HH; k += 32)
            d += (double)hrow[k] * (double)wrow[k];
        #pragma unroll
        for (int off = 16; off > 0; off >>= 1)
            d += __shfl_down_sync(0xFFFFFFFFu, d, off);
        if (lane == 0) sL[ci] = d + (double)bout[v];
    }
    __syncthreads();

    if (tid == 0) {
        if (n <= 1) {
            g_vstar[row] = (n == 1) ? g_candv[row * CAND_MAX]
                                    : (int)(0xFFFFFFFFu - (unsigned)(g_best[row] & 0xFFFFFFFFull));
        } else {
            double M = sL[0];
            for (int i = 1; i < n; ++i) if (sL[i] > M) M = sL[i];
            float Z = g_Z[row];
            float bestp = -1.0f;
            int bestv = 0x7FFFFFFF;
            for (int i = 0; i < n; ++i) {
                float e = (float)exp(sL[i] - M);        // emulate fp32 exp quantization
                float p = __fdiv_rn(e, Z);              // IEEE fp32 divide (fast-math safe)
                int v = g_candv[row * CAND_MAX + i];
                if (p > bestp || (p == bestp && v < bestv)) { bestp = p; bestv = v; }
            }
            g_vstar[row] = bestv;
        }
    }
}

// ---------------- kernel 4: gather transfer_weight rows ----------------------
__global__ void k_gather(const float* __restrict__ transfer, float* __restrict__ out) {
    int row = blockIdx.x;
    int vstar = g_vstar[row];
    const float* src = transfer + (size_t)vstar * EE;
    float* dst = out + (size_t)row * EE;
    for (int e = threadIdx.x; e < EE; e += blockDim.x) dst[e] = src[e];
}

// ---------------- launch ----------------
extern "C" void kernel_launch(void* const* d_in, const int* in_sizes, int n_in,
                              void* d_out, int out_size) {
    const int*   tokens    = (const int*)d_in[0];
    const int*   relations = (const int*)d_in[1];
    const float* hiddens   = (const float*)d_in[2];
    const float* embed     = (const float*)d_in[3];
    const float* transfer  = (const float*)d_in[4];
    const float* rel_emb   = (const float*)d_in[5];
    const float* W_ih      = (const float*)d_in[6];
    const float* W_hh      = (const float*)d_in[7];
    const float* b_ih      = (const float*)d_in[8];
    const float* b_hh      = (const float*)d_in[9];
    const float* W_out     = (const float*)d_in[10];
    const float* b_out     = (const float*)d_in[11];
    float* out = (float*)d_out;

    k_zero<<<8, 256>>>();
    k_xseq<<<MM, 384>>>(tokens, relations, embed, rel_emb);

    size_t smem = (size_t)(16 * 880 + 880 * 8 + 16 * 16 * 8 + 16 * 8 + 4 * 8 + 16) * sizeof(float);
    cudaFuncSetAttribute(k_lstm, cudaFuncAttributeMaxDynamicSharedMemorySize, (int)smem);
    k_lstm<<<LSTM_BLOCKS, 256, smem>>>(hiddens, W_ih, W_hh, b_ih, b_hh);

    k_logits<<<dim3(VV / BV, MM / BM), 256>>>(W_out, b_out);
    k_scan<<<MM, 256>>>();
    k_rescore<<<MM, 256>>>(W_out, b_out);
    k_gather<<<MM, 128>>>(transfer, out);
}

// round 10
// speedup vs baseline: 1.4503x; 1.4503x over previous
#include <cuda_runtime.h>
#include <cuda_bf16.h>
#include <cstdint>

// ---------------- problem constants ----------------
#define SQ   256
#define BB   8
#define VV   32000
#define EE   300
#define HH   512
#define ERD  64
#define XDIM (EE + ERD)     // 364
#define XH   (XDIM + HH)    // 876
#define MM   (SQ * BB)      // 2048

#define LSTM_BLOCKS 128
#define HPB 4
#define KCH 55

#define CAND_MAX 64
#define CAND_EPS 5e-4f      // R4-validated margin for fp32 logits

// ---------------- scratch ----------------
__device__ float g_xseq[MM * XDIM];
__device__ float g_hs[MM * HH];
__device__ float g_logits[(size_t)MM * VV];    // 262 MB bss
__device__ unsigned long long g_best[MM];
__device__ float g_Z[MM];
__device__ int   g_candv[MM * CAND_MAX];
__device__ int   g_candn[MM];
__device__ int   g_vstar[MM];
__device__ unsigned g_bars[SQ];

// ---------------- helpers ----------------
__device__ __forceinline__ void ffma2(unsigned long long &d, unsigned long long a,
                                      unsigned long long b) {
    asm("fma.rn.f32x2 %0, %1, %2, %0;" : "+l"(d) : "l"(a), "l"(b));
}
__device__ __forceinline__ unsigned long long dup2(float f) {
    unsigned long long d;
    asm("mov.b64 %0, {%1, %1};" : "=l"(d) : "f"(f));
    return d;
}
__device__ __forceinline__ float2 unpack2(unsigned long long a) {
    float2 f;
    asm("mov.b64 {%0, %1}, %2;" : "=f"(f.x), "=f"(f.y) : "l"(a));
    return f;
}
__device__ __forceinline__ unsigned long long make_key(float logit, int v) {
    unsigned u = __float_as_uint(logit);
    u = (u & 0x80000000u) ? ~u : (u | 0x80000000u);
    return ((unsigned long long)u << 32) | (unsigned)(0xFFFFFFFFu - (unsigned)v);
}
__device__ __forceinline__ float key_to_float(unsigned long long key) {
    unsigned u = (unsigned)(key >> 32);
    unsigned fb = (u & 0x80000000u) ? (u ^ 0x80000000u) : ~u;
    return __uint_as_float(fb);
}

// ---------------- kernel 0: zero state ----------------
__global__ void k_zero() {
    int t = blockIdx.x * blockDim.x + threadIdx.x;
    if (t < MM) { g_best[t] = 0ull; g_candn[t] = 0; }
    if (t < SQ) g_bars[t] = 0u;
}

// ---------------- kernel 1: x_seq ----------------
__global__ void k_xseq(const int* __restrict__ tokens, const int* __restrict__ relations,
                       const float* __restrict__ embed, const float* __restrict__ rel_emb) {
    int sb = blockIdx.x;
    int s = sb >> 3, b = sb & 7;
    int k = threadIdx.x;
    if (k >= XDIM) return;
    float val;
    if (k < ERD) {
        int r = relations[s * BB + b];
        val = rel_emb[r * ERD + k];
    } else {
        int tok = (s == 0) ? 0 : tokens[(s - 1) * BB + b];
        val = embed[tok * EE + (k - ERD)];
    }
    g_xseq[sb * XDIM + k] = val;
}

// ---------------- kernel 2: persistent LSTM (R4-validated) ----------------
__global__ __launch_bounds__(256, 1) void k_lstm(
    const float* __restrict__ hiddens,
    const float* __restrict__ W_ih, const float* __restrict__ W_hh,
    const float* __restrict__ b_ih, const float* __restrict__ b_hh) {
    extern __shared__ float sm[];
    float* w_s    = sm;
    float* xh_s   = w_s + 16 * 880;
    float* part_s = xh_s + 880 * 8;
    float* gate_s = part_s + 16 * 16 * 8;
    float* c_s    = gate_s + 16 * 8;
    float* bias_s = c_s + 4 * 8;

    const int tid = threadIdx.x;
    const int j0 = blockIdx.x * HPB;

    for (int idx = tid; idx < 16 * XH; idx += 256) {
        int r = idx / XH, k = idx - r * XH;
        int g = r >> 2, jj = r & 3;
        int row = g * HH + j0 + jj;
        float v = (k < XDIM) ? W_ih[row * XDIM + k] : W_hh[row * HH + (k - XDIM)];
        w_s[r * 880 + k] = v;
    }
    if (tid < 16) {
        int g = tid >> 2, jj = tid & 3;
        int row = g * HH + j0 + jj;
        bias_s[tid] = b_ih[row] + b_hh[row];
    }
    if (tid < 32) {
        int jj = tid >> 3, b = tid & 7;
        c_s[jj * 8 + b] = hiddens[b * HH + j0 + jj];
    }
    __syncthreads();

    const int r = tid >> 4;
    const int c = tid & 15;
    const int kbeg = c * KCH;
    const int kend = (kbeg + KCH < XH) ? (kbeg + KCH) : XH;
    const float* wrow = w_s + r * 880;

    for (int s = 0; s < SQ; ++s) {
        for (int idx = tid; idx < XH * BB; idx += 256) {
            int k = idx >> 3, b = idx & 7;
            float v;
            if (k < XDIM) {
                v = g_xseq[(s * BB + b) * XDIM + k];
            } else {
                int hk = k - XDIM;
                v = (s == 0) ? hiddens[b * HH + hk]
                             : __ldcg(&g_hs[((s - 1) * BB + b) * HH + hk]);
            }
            xh_s[k * 8 + b] = v;
        }
        __syncthreads();

        unsigned long long a0 = 0ull, a1 = 0ull, a2 = 0ull, a3 = 0ull;
        #pragma unroll 5
        for (int k = kbeg; k < kend; ++k) {
            unsigned long long ww = dup2(wrow[k]);
            const ulonglong2* xp = (const ulonglong2*)(xh_s + k * 8);
            ulonglong2 x01 = xp[0];
            ulonglong2 x23 = xp[1];
            ffma2(a0, x01.x, ww);
            ffma2(a1, x01.y, ww);
            ffma2(a2, x23.x, ww);
            ffma2(a3, x23.y, ww);
        }
        unsigned long long* pp = (unsigned long long*)(part_s + (r * 16 + c) * 8);
        pp[0] = a0; pp[1] = a1; pp[2] = a2; pp[3] = a3;
        __syncthreads();

        if (tid < 128) {
            int rr2 = tid >> 3, b = tid & 7;
            float acc = bias_s[rr2];
            #pragma unroll
            for (int cc = 0; cc < 16; ++cc) acc += part_s[(rr2 * 16 + cc) * 8 + b];
            gate_s[rr2 * 8 + b] = acc;
        }
        __syncthreads();

        if (tid < 32) {
            int jj = tid >> 3, b = tid & 7;
            double gi = (double)gate_s[(0 * 4 + jj) * 8 + b];
            double gf = (double)gate_s[(1 * 4 + jj) * 8 + b];
            double gg = (double)gate_s[(2 * 4 + jj) * 8 + b];
            double go = (double)gate_s[(3 * 4 + jj) * 8 + b];
            double cold = (double)c_s[jj * 8 + b];
            double si = 1.0 / (1.0 + exp(-gi));
            double sf = 1.0 / (1.0 + exp(-gf));
            double so = 1.0 / (1.0 + exp(-go));
            double cn = sf * cold + si * tanh(gg);
            float cnf = (float)cn;
            float hnf = (float)(so * tanh((double)cnf));
            c_s[jj * 8 + b] = cnf;
            g_hs[(s * BB + b) * HH + j0 + jj] = hnf;
        }
        __syncthreads();

        if (s != SQ - 1) {
            if (tid == 0) {
                __threadfence();
                unsigned arr = atomicAdd(&g_bars[s], 1u) + 1u;
                if (arr < (unsigned)LSTM_BLOCKS) {
                    while (*((volatile unsigned*)&g_bars[s]) < (unsigned)LSTM_BLOCKS) { }
                }
            }
            __syncthreads();
        }
    }
}

// ---------------- kernel 3: conflict-free fp32 f32x2 logits GEMM -------------
// CTA 64m x 128n, BK=16. 256 threads; thread = 4m x 8n (n strided by 16).
// Inner-loop LDS: sW reads are 16 consecutive floats per half-warp (conflict-
// free + broadcast); sA reads are 2-address 16B broadcasts. w duplicated in
// REGISTERS (mov.b64), not smem — kills R4's 4-way conflicts (L1 98.8%).
// Numerics identical to the R4 pass: sequential fp32 fma over k=0..511 + bias.
#define BMX 64
#define BNX 128
#define BKX 16

__global__ __launch_bounds__(256, 2) void k_logits(const float* __restrict__ Wout,
                                                   const float* __restrict__ bout) {
    __shared__ float sA[BKX * BMX];                  // [k][m] 4KB
    __shared__ float sW[BKX * BNX];                  // [k][n] 8KB
    __shared__ unsigned long long sKey[BMX];

    const int tid = threadIdx.x;
    const int n0 = blockIdx.x * BNX;
    const int m0 = blockIdx.y * BMX;
    const int tm = tid >> 4;            // 0..15 -> m = tm*4 .. +3
    const int tn = tid & 15;            // n = tn + j*16

    if (tid < BMX) sKey[tid] = 0ull;

    // staging assignments
    const int ar = tid >> 2;            // 0..63  (A row)
    const int ak = (tid & 3) * 4;       // k sub
    const int wr = tid >> 1;            // 0..127 (W row = v)
    const int wk = (tid & 1) * 8;       // k sub
    const float* gA = g_hs + (size_t)(m0 + ar) * HH + ak;
    const float* gW = Wout + (size_t)(n0 + wr) * HH + wk;

    unsigned long long acc[2][8];
    #pragma unroll
    for (int p = 0; p < 2; ++p)
        #pragma unroll
        for (int j = 0; j < 8; ++j) acc[p][j] = 0ull;

    float4 pa  = *(const float4*)gA;
    float4 pw0 = *(const float4*)gW;
    float4 pw1 = *(const float4*)(gW + 4);

    const int NT = HH / BKX;            // 32
    for (int t = 0; t < NT; ++t) {
        sA[(ak + 0) * BMX + ar] = pa.x;
        sA[(ak + 1) * BMX + ar] = pa.y;
        sA[(ak + 2) * BMX + ar] = pa.z;
        sA[(ak + 3) * BMX + ar] = pa.w;
        sW[(wk + 0) * BNX + wr] = pw0.x;
        sW[(wk + 1) * BNX + wr] = pw0.y;
        sW[(wk + 2) * BNX + wr] = pw0.z;
        sW[(wk + 3) * BNX + wr] = pw0.w;
        sW[(wk + 4) * BNX + wr] = pw1.x;
        sW[(wk + 5) * BNX + wr] = pw1.y;
        sW[(wk + 6) * BNX + wr] = pw1.z;
        sW[(wk + 7) * BNX + wr] = pw1.w;
        __syncthreads();
        if (t + 1 < NT) {
            pa  = *(const float4*)(gA + (t + 1) * BKX);
            pw0 = *(const float4*)(gW + (t + 1) * BKX);
            pw1 = *(const float4*)(gW + (t + 1) * BKX + 4);
        }
        #pragma unroll
        for (int k = 0; k < BKX; ++k) {
            ulonglong2 av = *(const ulonglong2*)(sA + k * BMX + tm * 4);
            #pragma unroll
            for (int j = 0; j < 8; ++j) {
                unsigned long long wd = dup2(sW[k * BNX + tn + j * 16]);
                ffma2(acc[0][j], av.x, wd);
                ffma2(acc[1][j], av.y, wd);
            }
        }
        __syncthreads();
    }

    // epilogue: +bias, store fp32 logits, per-row argmax keys
    float bias[8];
    #pragma unroll
    for (int j = 0; j < 8; ++j) bias[j] = __ldg(&bout[n0 + tn + j * 16]);

    #pragma unroll
    for (int p = 0; p < 2; ++p) {
        #pragma unroll
        for (int half = 0; half < 2; ++half) {
            int m_loc = tm * 4 + p * 2 + half;
            float* lrow = g_logits + (size_t)(m0 + m_loc) * VV + n0;
            unsigned long long best = 0ull;
            #pragma unroll
            for (int j = 0; j < 8; ++j) {
                float2 f = unpack2(acc[p][j]);
                float l = (half == 0 ? f.x : f.y) + bias[j];
                lrow[tn + j * 16] = l;
                unsigned long long key = make_key(l, n0 + tn + j * 16);
                if (key > best) best = key;
            }
            atomicMax(&sKey[m_loc], best);
        }
    }
    __syncthreads();
    if (tid < BMX) atomicMax(&g_best[m0 + tid], sKey[tid]);
}

// ---------------- kernel 3b: per-row Z + candidates ----------------
__global__ __launch_bounds__(256) void k_scan() {
    const int row = blockIdx.x;
    const int tid = threadIdx.x;
    __shared__ float sSum[256];
    __shared__ int sCnt;
    if (tid == 0) sCnt = 0;
    __syncthreads();

    const float rowmax = key_to_float(g_best[row]);
    const float th = rowmax - CAND_EPS;
    const float* lrow = g_logits + (size_t)row * VV;

    float acc = 0.0f;
    for (int v = tid; v < VV; v += 256) {
        float l = lrow[v];
        acc += expf(l - rowmax);
        if (l >= th) {
            int idx = atomicAdd(&sCnt, 1);
            if (idx < CAND_MAX) g_candv[row * CAND_MAX + idx] = v;
        }
    }
    sSum[tid] = acc;
    __syncthreads();
    for (int st = 128; st > 0; st >>= 1) {
        if (tid < st) sSum[tid] += sSum[tid + st];
        __syncthreads();
    }
    if (tid == 0) {
        g_Z[row] = sSum[0];
        g_candn[row] = (sCnt < CAND_MAX) ? sCnt : CAND_MAX;
    }
}

// ---------------- kernel 3c: fp64 rescore + quantized-softmax argmax ---------
__global__ __launch_bounds__(256) void k_rescore(const float* __restrict__ Wout,
                                                 const float* __restrict__ bout) {
    const int row = blockIdx.x;
    const int tid = threadIdx.x;
    const int warp = tid >> 5, lane = tid & 31;
    __shared__ double sL[CAND_MAX];

    const int n = g_candn[row];
    const float* hrow = g_hs + (size_t)row * HH;

    for (int ci = warp; ci < n; ci += 8) {
        int v = g_candv[row * CAND_MAX + ci];
        const float* wrow = Wout + (size_t)v * HH;
        double d = 0.0;
        #pragma unroll
        for (int k = lane; k < HH; k += 32)
            d += (double)hrow[k] * (double)wrow[k];
        #pragma unroll
        for (int off = 16; off > 0; off >>= 1)
            d += __shfl_down_sync(0xFFFFFFFFu, d, off);
        if (lane == 0) sL[ci] = d + (double)bout[v];
    }
    __syncthreads();

    if (tid == 0) {
        if (n <= 1) {
            g_vstar[row] = (n == 1) ? g_candv[row * CAND_MAX]
                                    : (int)(0xFFFFFFFFu - (unsigned)(g_best[row] & 0xFFFFFFFFull));
        } else {
            double M = sL[0];
            for (int i = 1; i < n; ++i) if (sL[i] > M) M = sL[i];
            float Z = g_Z[row];
            float bestp = -1.0f;
            int bestv = 0x7FFFFFFF;
            for (int i = 0; i < n; ++i) {
                float e = (float)exp(sL[i] - M);
                float p = __fdiv_rn(e, Z);
                int v = g_candv[row * CAND_MAX + i];
                if (p > bestp || (p == bestp && v < bestv)) { bestp = p; bestv = v; }
            }
            g_vstar[row] = bestv;
        }
    }
}

// ---------------- kernel 4: gather ----------------
__global__ void k_gather(const float* __restrict__ transfer, float* __restrict__ out) {
    int row = blockIdx.x;
    int vstar = g_vstar[row];
    const float* src = transfer + (size_t)vstar * EE;
    float* dst = out + (size_t)row * EE;
    for (int e = threadIdx.x; e < EE; e += blockDim.x) dst[e] = src[e];
}

// ---------------- launch ----------------
extern "C" void kernel_launch(void* const* d_in, const int* in_sizes, int n_in,
                              void* d_out, int out_size) {
    const int*   tokens    = (const int*)d_in[0];
    const int*   relations = (const int*)d_in[1];
    const float* hiddens   = (const float*)d_in[2];
    const float* embed     = (const float*)d_in[3];
    const float* transfer  = (const float*)d_in[4];
    const float* rel_emb   = (const float*)d_in[5];
    const float* W_ih      = (const float*)d_in[6];
    const float* W_hh      = (const float*)d_in[7];
    const float* b_ih      = (const float*)d_in[8];
    const float* b_hh      = (const float*)d_in[9];
    const float* W_out     = (const float*)d_in[10];
    const float* b_out     = (const float*)d_in[11];
    float* out = (float*)d_out;

    k_zero<<<8, 256>>>();
    k_xseq<<<MM, 384>>>(tokens, relations, embed, rel_emb);

    size_t smem = (size_t)(16 * 880 + 880 * 8 + 16 * 16 * 8 + 16 * 8 + 4 * 8 + 16) * sizeof(float);
    cudaFuncSetAttribute(k_lstm, cudaFuncAttributeMaxDynamicSharedMemorySize, (int)smem);
    k_lstm<<<LSTM_BLOCKS, 256, smem>>>(hiddens, W_ih, W_hh, b_ih, b_hh);

    k_logits<<<dim3(VV / BNX, MM / BMX), 256>>>(W_out, b_out);
    k_scan<<<MM, 256>>>();
    k_rescore<<<MM, 256>>>(W_out, b_out);
    k_gather<<<MM, 128>>>(transfer, out);
}

// round 11
// speedup vs baseline: 1.7992x; 1.2406x over previous
#include <cuda_runtime.h>
#include <cuda_bf16.h>
#include <cstdint>

// ---------------- problem constants ----------------
#define SQ   256
#define BB   8
#define VV   32000
#define EE   300
#define HH   512
#define ERD  64
#define XDIM (EE + ERD)     // 364
#define XH   (XDIM + HH)    // 876
#define MM   (SQ * BB)      // 2048

#define LSTM_BLOCKS 128
#define HPB 4
#define NI  55              // k-slices per thread: k = 16*i + c, KPAD=880

#define CAND_MAX 64
#define CAND_EPS 5e-4f      // R4/R10-validated margin for fp32 logits

// ---------------- scratch ----------------
__device__ float g_xseq[MM * XDIM];
__device__ float g_hs[MM * HH];
__device__ float g_logits[(size_t)MM * VV];    // 262 MB bss
__device__ unsigned long long g_best[MM];
__device__ float g_Z[MM];
__device__ int   g_candv[MM * CAND_MAX];
__device__ int   g_candn[MM];
__device__ int   g_vstar[MM];
__device__ unsigned g_bars[SQ];

// ---------------- helpers ----------------
__device__ __forceinline__ void ffma2(unsigned long long &d, unsigned long long a,
                                      unsigned long long b) {
    asm("fma.rn.f32x2 %0, %1, %2, %0;" : "+l"(d) : "l"(a), "l"(b));
}
__device__ __forceinline__ unsigned long long dup2(float f) {
    unsigned long long d;
    asm("mov.b64 %0, {%1, %1};" : "=l"(d) : "f"(f));
    return d;
}
__device__ __forceinline__ float2 unpack2(unsigned long long a) {
    float2 f;
    asm("mov.b64 {%0, %1}, %2;" : "=f"(f.x), "=f"(f.y) : "l"(a));
    return f;
}
__device__ __forceinline__ unsigned long long make_key(float logit, int v) {
    unsigned u = __float_as_uint(logit);
    u = (u & 0x80000000u) ? ~u : (u | 0x80000000u);
    return ((unsigned long long)u << 32) | (unsigned)(0xFFFFFFFFu - (unsigned)v);
}
__device__ __forceinline__ float key_to_float(unsigned long long key) {
    unsigned u = (unsigned)(key >> 32);
    unsigned fb = (u & 0x80000000u) ? (u ^ 0x80000000u) : ~u;
    return __uint_as_float(fb);
}

// ---------------- kernel 0: zero state ----------------
__global__ void k_zero() {
    int t = blockIdx.x * blockDim.x + threadIdx.x;
    if (t < MM) { g_best[t] = 0ull; g_candn[t] = 0; }
    if (t < SQ) g_bars[t] = 0u;
}

// ---------------- kernel 1: x_seq ----------------
__global__ void k_xseq(const int* __restrict__ tokens, const int* __restrict__ relations,
                       const float* __restrict__ embed, const float* __restrict__ rel_emb) {
    int sb = blockIdx.x;
    int s = sb >> 3, b = sb & 7;
    int k = threadIdx.x;
    if (k >= XDIM) return;
    float val;
    if (k < ERD) {
        int r = relations[s * BB + b];
        val = rel_emb[r * ERD + k];
    } else {
        int tok = (s == 0) ? 0 : tokens[(s - 1) * BB + b];
        val = embed[tok * EE + (k - ERD)];
    }
    g_xseq[sb * XDIM + k] = val;
}

// ---------------- kernel 2: persistent LSTM v2 ----------------
// Weights in REGISTERS (55/thread, constant over all 256 steps).
// xh in smem, layout addr(k,b) = (k>>4)*128 + (k&15)*8 + b  (floats):
// thread (r=tid>>4, c=tid&15) reads k=16i+c -> warp reads 512B contiguous,
// conflict-free. shfl reduction over c. Double-buffered x staging overlaps
// the grid-barrier spin.
#define XH2_FLOATS (NI * 128)        // 7040 floats per buffer
__device__ __forceinline__ int xh_off(int k, int b) {
    return (k >> 4) * 128 + (k & 15) * 8 + b;
}

__global__ __launch_bounds__(256, 1) void k_lstm(
    const float* __restrict__ hiddens,
    const float* __restrict__ W_ih, const float* __restrict__ W_hh,
    const float* __restrict__ b_ih, const float* __restrict__ b_hh) {
    extern __shared__ float sm[];
    float* xhA    = sm;                        // 7040
    float* xhB    = xhA + XH2_FLOATS;          // 7040
    float* gate_s = xhB + XH2_FLOATS;          // 128 (16 rows x 8 b)
    float* c_s    = gate_s + 128;              // 32
    float* bias_s = c_s + 32;                  // 16

    const int tid = threadIdx.x;
    const int r = tid >> 4;          // gate row 0..15
    const int c = tid & 15;          // k-slice
    const int j0 = blockIdx.x * HPB;
    const int gate = r >> 2, jj = r & 3;
    const int grow = gate * HH + j0 + jj;

    // per-thread weight slice: k = 16*i + c
    float wreg[NI];
    #pragma unroll
    for (int i = 0; i < NI; ++i) {
        int k = 16 * i + c;
        wreg[i] = (k < XDIM) ? W_ih[grow * XDIM + k]
                : (k < XH)   ? W_hh[grow * HH + (k - XDIM)] : 0.0f;
    }
    if (tid < 16) {
        int g2 = tid >> 2, j2 = tid & 3;
        int row = g2 * HH + j0 + j2;
        bias_s[tid] = b_ih[row] + b_hh[row];
    }
    if (tid < 32) {
        int j2 = tid >> 3, b = tid & 7;
        c_s[j2 * 8 + b] = hiddens[b * HH + j0 + j2];
    }
    // zero pad region k=876..879 in both buffers
    if (tid < 64) {
        int buf = tid >> 5, kk = 876 + ((tid >> 3) & 3), b = tid & 7;
        (buf ? xhB : xhA)[xh_off(kk, b)] = 0.0f;
    }
    // stage x_0 into buffer A
    for (int idx = tid; idx < XDIM * 8; idx += 256) {
        int k = idx >> 3, b = idx & 7;
        xhA[xh_off(k, b)] = g_xseq[b * XDIM + k];      // s=0 row
    }
    __syncthreads();

    float* cur = xhA;
    float* nxt = xhB;
    const unsigned long long ONE2 = dup2(1.0f);

    for (int s = 0; s < SQ; ++s) {
        // (1) stage h_{s-1} into cur (k = 364..875)
        {
            int b = tid & 7, m = tid >> 3;            // m 0..31
            const float* src = (s == 0) ? (hiddens + b * HH + m * 16)
                                        : (g_hs + (size_t)((s - 1) * 8 + b) * HH + m * 16);
            float4 v0, v1, v2, v3;
            if (s == 0) {
                v0 = *(const float4*)(src);      v1 = *(const float4*)(src + 4);
                v2 = *(const float4*)(src + 8);  v3 = *(const float4*)(src + 12);
            } else {
                v0 = __ldcg((const float4*)(src));
                v1 = __ldcg((const float4*)(src + 4));
                v2 = __ldcg((const float4*)(src + 8));
                v3 = __ldcg((const float4*)(src + 12));
            }
            float vals[16] = {v0.x, v0.y, v0.z, v0.w, v1.x, v1.y, v1.z, v1.w,
                              v2.x, v2.y, v2.z, v2.w, v3.x, v3.y, v3.z, v3.w};
            #pragma unroll
            for (int j = 0; j < 16; ++j)
                cur[xh_off(XDIM + m * 16 + j, b)] = vals[j];
        }
        __syncthreads();

        // (3) gates: per-thread partial over its 55 k-slices
        unsigned long long a0 = 0ull, a1 = 0ull, a2 = 0ull, a3 = 0ull;
        const float* base = cur + c * 8;
        #pragma unroll
        for (int i = 0; i < NI; ++i) {
            ulonglong2 x01 = *(const ulonglong2*)(base + i * 128);
            ulonglong2 x23 = *(const ulonglong2*)(base + i * 128 + 4);
            unsigned long long ww = dup2(wreg[i]);
            ffma2(a0, x01.x, ww);
            ffma2(a1, x01.y, ww);
            ffma2(a2, x23.x, ww);
            ffma2(a3, x23.y, ww);
        }
        // shfl-reduce over c (16 lanes per half-warp)
        #pragma unroll
        for (int mask = 1; mask < 16; mask <<= 1) {
            unsigned long long t0 = __shfl_xor_sync(0xFFFFFFFFu, a0, mask);
            unsigned long long t1 = __shfl_xor_sync(0xFFFFFFFFu, a1, mask);
            unsigned long long t2 = __shfl_xor_sync(0xFFFFFFFFu, a2, mask);
            unsigned long long t3 = __shfl_xor_sync(0xFFFFFFFFu, a3, mask);
            ffma2(a0, t0, ONE2);
            ffma2(a1, t1, ONE2);
            ffma2(a2, t2, ONE2);
            ffma2(a3, t3, ONE2);
        }
        if (c == 0) {
            unsigned long long* gs = (unsigned long long*)gate_s + r * 4;
            gs[0] = a0; gs[1] = a1; gs[2] = a2; gs[3] = a3;
        }
        __syncthreads();

        // (5) cell update (double precision, R10-validated)
        if (tid < 32) {
            int j2 = tid >> 3, b = tid & 7;
            double gi = (double)(gate_s[(0 * 4 + j2) * 8 + b] + bias_s[0 * 4 + j2]);
            double gf = (double)(gate_s[(1 * 4 + j2) * 8 + b] + bias_s[1 * 4 + j2]);
            double gg = (double)(gate_s[(2 * 4 + j2) * 8 + b] + bias_s[2 * 4 + j2]);
            double go = (double)(gate_s[(3 * 4 + j2) * 8 + b] + bias_s[3 * 4 + j2]);
            double cold = (double)c_s[j2 * 8 + b];
            double si = 1.0 / (1.0 + exp(-gi));
            double sf = 1.0 / (1.0 + exp(-gf));
            double so = 1.0 / (1.0 + exp(-go));
            double cn = sf * cold + si * tanh(gg);
            float cnf = (float)cn;
            float hnf = (float)(so * tanh((double)cnf));
            c_s[j2 * 8 + b] = cnf;
            g_hs[(size_t)(s * 8 + b) * HH + j0 + j2] = hnf;
        }
        __syncthreads();

        if (s + 1 < SQ) {
            // (7) stage x_{s+1} into nxt (overlaps barrier spin below)
            for (int idx = tid; idx < XDIM * 8; idx += 256) {
                int k = idx >> 3, b = idx & 7;
                nxt[xh_off(k, b)] = g_xseq[(size_t)((s + 1) * 8 + b) * XDIM + k];
            }
            // (8) grid barrier
            if (tid == 0) {
                __threadfence();
                unsigned arr = atomicAdd(&g_bars[s], 1u) + 1u;
                if (arr < (unsigned)LSTM_BLOCKS) {
                    while (*((volatile unsigned*)&g_bars[s]) < (unsigned)LSTM_BLOCKS) { }
                }
            }
            __syncthreads();
        }
        float* tmp = cur; cur = nxt; nxt = tmp;
    }
}

// ---------------- kernel 3: fp32 f32x2 logits GEMM (n-paired accs) ----------
// Same math as R10 (sequential fp32 fma over k, bias at end -> bitwise
// identical logits). Accumulators pack n-pairs so w loads are direct u64 LDS
// (no per-w dup2): 25 issues / 16 ffma2 vs 33 before.
#define BMX 64
#define BNX 128
#define BKX 16

__global__ __launch_bounds__(256, 2) void k_logits(const float* __restrict__ Wout,
                                                   const float* __restrict__ bout) {
    __shared__ float sA[BKX * BMX];                  // [k][m]
    __shared__ float sW[BKX * BNX];                  // [k][n]
    __shared__ unsigned long long sKey[BMX];

    const int tid = threadIdx.x;
    const int n0 = blockIdx.x * BNX;
    const int m0 = blockIdx.y * BMX;
    const int tm = tid >> 4;            // m = tm*4 + 0..3
    const int tn = tid & 15;            // n = tn*8 + 0..7

    if (tid < BMX) sKey[tid] = 0ull;

    const int ar = tid >> 2;            // A staging row
    const int ak = (tid & 3) * 4;
    const int wr = tid >> 1;            // W staging row (= n)
    const int wk = (tid & 1) * 8;
    const float* gA = g_hs + (size_t)(m0 + ar) * HH + ak;
    const float* gW = Wout + (size_t)(n0 + wr) * HH + wk;

    unsigned long long acc[4][4];
    #pragma unroll
    for (int m = 0; m < 4; ++m)
        #pragma unroll
        for (int j = 0; j < 4; ++j) acc[m][j] = 0ull;

    float4 pa  = *(const float4*)gA;
    float4 pw0 = *(const float4*)gW;
    float4 pw1 = *(const float4*)(gW + 4);

    const int NT = HH / BKX;            // 32
    for (int t = 0; t < NT; ++t) {
        sA[(ak + 0) * BMX + ar] = pa.x;
        sA[(ak + 1) * BMX + ar] = pa.y;
        sA[(ak + 2) * BMX + ar] = pa.z;
        sA[(ak + 3) * BMX + ar] = pa.w;
        sW[(wk + 0) * BNX + wr] = pw0.x;
        sW[(wk + 1) * BNX + wr] = pw0.y;
        sW[(wk + 2) * BNX + wr] = pw0.z;
        sW[(wk + 3) * BNX + wr] = pw0.w;
        sW[(wk + 4) * BNX + wr] = pw1.x;
        sW[(wk + 5) * BNX + wr] = pw1.y;
        sW[(wk + 6) * BNX + wr] = pw1.z;
        sW[(wk + 7) * BNX + wr] = pw1.w;
        __syncthreads();
        if (t + 1 < NT) {
            pa  = *(const float4*)(gA + (t + 1) * BKX);
            pw0 = *(const float4*)(gW + (t + 1) * BKX);
            pw1 = *(const float4*)(gW + (t + 1) * BKX + 4);
        }
        #pragma unroll
        for (int k = 0; k < BKX; ++k) {
            float4 av = *(const float4*)(sA + k * BMX + tm * 4);
            ulonglong2 w01 = *(const ulonglong2*)(sW + k * BNX + tn * 8);
            ulonglong2 w23 = *(const ulonglong2*)(sW + k * BNX + tn * 8 + 4);
            unsigned long long am;
            am = dup2(av.x);
            ffma2(acc[0][0], w01.x, am); ffma2(acc[0][1], w01.y, am);
            ffma2(acc[0][2], w23.x, am); ffma2(acc[0][3], w23.y, am);
            am = dup2(av.y);
            ffma2(acc[1][0], w01.x, am); ffma2(acc[1][1], w01.y, am);
            ffma2(acc[1][2], w23.x, am); ffma2(acc[1][3], w23.y, am);
            am = dup2(av.z);
            ffma2(acc[2][0], w01.x, am); ffma2(acc[2][1], w01.y, am);
            ffma2(acc[2][2], w23.x, am); ffma2(acc[2][3], w23.y, am);
            am = dup2(av.w);
            ffma2(acc[3][0], w01.x, am); ffma2(acc[3][1], w01.y, am);
            ffma2(acc[3][2], w23.x, am); ffma2(acc[3][3], w23.y, am);
        }
        __syncthreads();
    }

    // epilogue: +bias, store fp32 logits (32B/thread/m contiguous), argmax keys
    float bias[8];
    #pragma unroll
    for (int j = 0; j < 8; ++j) bias[j] = __ldg(&bout[n0 + tn * 8 + j]);

    #pragma unroll
    for (int m = 0; m < 4; ++m) {
        int m_loc = tm * 4 + m;
        float l[8];
        #pragma unroll
        for (int j = 0; j < 4; ++j) {
            float2 f = unpack2(acc[m][j]);
            l[2 * j]     = f.x + bias[2 * j];
            l[2 * j + 1] = f.y + bias[2 * j + 1];
        }
        float* lrow = g_logits + (size_t)(m0 + m_loc) * VV + n0 + tn * 8;
        *(float4*)(lrow)     = make_float4(l[0], l[1], l[2], l[3]);
        *(float4*)(lrow + 4) = make_float4(l[4], l[5], l[6], l[7]);
        unsigned long long best = 0ull;
        #pragma unroll
        for (int j = 0; j < 8; ++j) {
            unsigned long long key = make_key(l[j], n0 + tn * 8 + j);
            if (key > best) best = key;
        }
        atomicMax(&sKey[m_loc], best);
    }
    __syncthreads();
    if (tid < BMX) atomicMax(&g_best[m0 + tid], sKey[tid]);
}

// ---------------- kernel 3b: per-row Z + candidates ----------------
__global__ __launch_bounds__(256) void k_scan() {
    const int row = blockIdx.x;
    const int tid = threadIdx.x;
    __shared__ float sSum[256];
    __shared__ int sCnt;
    if (tid == 0) sCnt = 0;
    __syncthreads();

    const float rowmax = key_to_float(g_best[row]);
    const float th = rowmax - CAND_EPS;
    const float* lrow = g_logits + (size_t)row * VV;

    float acc = 0.0f;
    for (int v = tid; v < VV; v += 256) {
        float l = lrow[v];
        acc += expf(l - rowmax);
        if (l >= th) {
            int idx = atomicAdd(&sCnt, 1);
            if (idx < CAND_MAX) g_candv[row * CAND_MAX + idx] = v;
        }
    }
    sSum[tid] = acc;
    __syncthreads();
    for (int st = 128; st > 0; st >>= 1) {
        if (tid < st) sSum[tid] += sSum[tid + st];
        __syncthreads();
    }
    if (tid == 0) {
        g_Z[row] = sSum[0];
        g_candn[row] = (sCnt < CAND_MAX) ? sCnt : CAND_MAX;
    }
}

// ---------------- kernel 3c: fp64 rescore + quantized-softmax argmax ---------
__global__ __launch_bounds__(256) void k_rescore(const float* __restrict__ Wout,
                                                 const float* __restrict__ bout) {
    const int row = blockIdx.x;
    const int tid = threadIdx.x;
    const int warp = tid >> 5, lane = tid & 31;
    __shared__ double sL[CAND_MAX];

    const int n = g_candn[row];
    const float* hrow = g_hs + (size_t)row * HH;

    for (int ci = warp; ci < n; ci += 8) {
        int v = g_candv[row * CAND_MAX + ci];
        const float* wrow = Wout + (size_t)v * HH;
        double d = 0.0;
        #pragma unroll
        for (int k = lane; k < HH; k += 32)
            d += (double)hrow[k] * (double)wrow[k];
        #pragma unroll
        for (int off = 16; off > 0; off >>= 1)
            d += __shfl_down_sync(0xFFFFFFFFu, d, off);
        if (lane == 0) sL[ci] = d + (double)bout[v];
    }
    __syncthreads();

    if (tid == 0) {
        if (n <= 1) {
            g_vstar[row] = (n == 1) ? g_candv[row * CAND_MAX]
                                    : (int)(0xFFFFFFFFu - (unsigned)(g_best[row] & 0xFFFFFFFFull));
        } else {
            double M = sL[0];
            for (int i = 1; i < n; ++i) if (sL[i] > M) M = sL[i];
            float Z = g_Z[row];
            float bestp = -1.0f;
            int bestv = 0x7FFFFFFF;
            for (int i = 0; i < n; ++i) {
                float e = (float)exp(sL[i] - M);
                float p = __fdiv_rn(e, Z);
                int v = g_candv[row * CAND_MAX + i];
                if (p > bestp || (p == bestp && v < bestv)) { bestp = p; bestv = v; }
            }
            g_vstar[row] = bestv;
        }
    }
}

// ---------------- kernel 4: gather ----------------
__global__ void k_gather(const float* __restrict__ transfer, float* __restrict__ out) {
    int row = blockIdx.x;
    int vstar = g_vstar[row];
    const float* src = transfer + (size_t)vstar * EE;
    float* dst = out + (size_t)row * EE;
    for (int e = threadIdx.x; e < EE; e += blockDim.x) dst[e] = src[e];
}

// ---------------- launch ----------------
extern "C" void kernel_launch(void* const* d_in, const int* in_sizes, int n_in,
                              void* d_out, int out_size) {
    const int*   tokens    = (const int*)d_in[0];
    const int*   relations = (const int*)d_in[1];
    const float* hiddens   = (const float*)d_in[2];
    const float* embed     = (const float*)d_in[3];
    const float* transfer  = (const float*)d_in[4];
    const float* rel_emb   = (const float*)d_in[5];
    const float* W_ih      = (const float*)d_in[6];
    const float* W_hh      = (const float*)d_in[7];
    const float* b_ih      = (const float*)d_in[8];
    const float* b_hh      = (const float*)d_in[9];
    const float* W_out     = (const float*)d_in[10];
    const float* b_out     = (const float*)d_in[11];
    float* out = (float*)d_out;

    k_zero<<<8, 256>>>();
    k_xseq<<<MM, 384>>>(tokens, relations, embed, rel_emb);

    size_t smem = (size_t)(2 * XH2_FLOATS + 128 + 32 + 16) * sizeof(float);
    cudaFuncSetAttribute(k_lstm, cudaFuncAttributeMaxDynamicSharedMemorySize, (int)smem);
    k_lstm<<<LSTM_BLOCKS, 256, smem>>>(hiddens, W_ih, W_hh, b_ih, b_hh);

    k_logits<<<dim3(VV / BNX, MM / BMX), 256>>>(W_out, b_out);
    k_scan<<<MM, 256>>>();
    k_rescore<<<MM, 256>>>(W_out, b_out);
    k_gather<<<MM, 128>>>(transfer, out);
}

// round 12
// speedup vs baseline: 2.5018x; 1.3905x over previous
#include <cuda_runtime.h>
#include <cuda_bf16.h>
#include <cstdint>

// ---------------- problem constants ----------------
#define SQ   256
#define BB   8
#define VV   32000
#define EE   300
#define HH   512
#define ERD  64
#define XDIM (EE + ERD)     // 364
#define XH   (XDIM + HH)    // 876
#define MM   (SQ * BB)      // 2048

#define LSTM_BLOCKS 64
#define HPB 8               // h indices per block
#define NI  55              // k-slices per thread: k = 16*i + c, KPAD=880

#define CAND_MAX 64
#define CAND_EPS 5e-4f

// ---------------- scratch ----------------
__device__ float g_xseq[MM * XDIM];
__device__ float g_hs[MM * HH];
__device__ float g_logits[(size_t)MM * VV];
__device__ unsigned long long g_best[MM];
__device__ float g_Z[MM];
__device__ int   g_candv[MM * CAND_MAX];
__device__ int   g_candn[MM];
__device__ int   g_vstar[MM];
__device__ unsigned g_bars[SQ];

// ---------------- helpers ----------------
__device__ __forceinline__ void ffma2(unsigned long long &d, unsigned long long a,
                                      unsigned long long b) {
    asm("fma.rn.f32x2 %0, %1, %2, %0;" : "+l"(d) : "l"(a), "l"(b));
}
__device__ __forceinline__ unsigned long long dup2(float f) {
    unsigned long long d;
    asm("mov.b64 %0, {%1, %1};" : "=l"(d) : "f"(f));
    return d;
}
__device__ __forceinline__ float2 unpack2(unsigned long long a) {
    float2 f;
    asm("mov.b64 {%0, %1}, %2;" : "=f"(f.x), "=f"(f.y) : "l"(a));
    return f;
}
__device__ __forceinline__ unsigned long long make_key(float logit, int v) {
    unsigned u = __float_as_uint(logit);
    u = (u & 0x80000000u) ? ~u : (u | 0x80000000u);
    return ((unsigned long long)u << 32) | (unsigned)(0xFFFFFFFFu - (unsigned)v);
}
__device__ __forceinline__ float key_to_float(unsigned long long key) {
    unsigned u = (unsigned)(key >> 32);
    unsigned fb = (u & 0x80000000u) ? (u ^ 0x80000000u) : ~u;
    return __uint_as_float(fb);
}

// ---------------- kernel 0: zero state ----------------
__global__ void k_zero() {
    int t = blockIdx.x * blockDim.x + threadIdx.x;
    if (t < MM) { g_best[t] = 0ull; g_candn[t] = 0; }
    if (t < SQ) g_bars[t] = 0u;
}

// ---------------- kernel 1: x_seq ----------------
__global__ void k_xseq(const int* __restrict__ tokens, const int* __restrict__ relations,
                       const float* __restrict__ embed, const float* __restrict__ rel_emb) {
    int sb = blockIdx.x;
    int s = sb >> 3, b = sb & 7;
    int k = threadIdx.x;
    if (k >= XDIM) return;
    float val;
    if (k < ERD) {
        int r = relations[s * BB + b];
        val = rel_emb[r * ERD + k];
    } else {
        int tok = (s == 0) ? 0 : tokens[(s - 1) * BB + b];
        val = embed[tok * EE + (k - ERD)];
    }
    g_xseq[sb * XDIM + k] = val;
}

// ---------------- kernel 2: persistent LSTM v3 ----------------
// 64 blocks x 256 threads. Block owns 8 h -> 32 gate rows. Thread (r=tid>>4,
// c=tid&15) handles gate rows r and r+16 over k-slices k=16i+c.
// xh layout: (k>>4)*128 + (b>>2)*64 + (k&15)*4 + (b&3)  -> compute reads are
// 16B at 16B lane stride across c = conflict-free.
#define XH2_FLOATS (NI * 128)        // 7040 floats per buffer
__device__ __forceinline__ int xh_off(int k, int b) {
    return (k >> 4) * 128 + (b >> 2) * 64 + (k & 15) * 4 + (b & 3);
}

__global__ __launch_bounds__(256, 1) void k_lstm(
    const float* __restrict__ hiddens,
    const float* __restrict__ W_ih, const float* __restrict__ W_hh,
    const float* __restrict__ b_ih, const float* __restrict__ b_hh) {
    extern __shared__ float sm[];
    float* xhA    = sm;                        // 7040
    float* xhB    = xhA + XH2_FLOATS;          // 7040
    float* gate_s = xhB + XH2_FLOATS;          // 256 (32 rows x 8 b)
    float* c_s    = gate_s + 256;              // 64
    float* bias_s = c_s + 64;                  // 32
    double* nl_s  = (double*)(bias_s + 32);    // 256 doubles

    const int tid = threadIdx.x;
    const int r = tid >> 4;          // 0..15
    const int c = tid & 15;
    const int j0 = blockIdx.x * HPB;

    // weight slices for rows r (gates i/f) and r+16 (gates g/o): k = 16*i + c
    float wA[NI], wB[NI];
    {
        const int rA = r, rB = r + 16;
        const int growA = (rA >> 3) * HH + j0 + (rA & 7);
        const int growB = (rB >> 3) * HH + j0 + (rB & 7);
        #pragma unroll
        for (int i = 0; i < NI; ++i) {
            int k = 16 * i + c;
            wA[i] = (k < XDIM) ? W_ih[growA * XDIM + k]
                  : (k < XH)   ? W_hh[growA * HH + (k - XDIM)] : 0.0f;
            wB[i] = (k < XDIM) ? W_ih[growB * XDIM + k]
                  : (k < XH)   ? W_hh[growB * HH + (k - XDIM)] : 0.0f;
        }
    }
    if (tid < 32) {
        int g2 = tid >> 3, j2 = tid & 7;
        bias_s[tid] = b_ih[g2 * HH + j0 + j2] + b_hh[g2 * HH + j0 + j2];
    }
    if (tid < 64) {
        int j2 = tid >> 3, b = tid & 7;
        c_s[tid] = hiddens[b * HH + j0 + j2];
    }
    if (tid < 64) {   // zero pad k=876..879 in both buffers
        int buf = tid >> 5, kk = 876 + ((tid >> 3) & 3), b = tid & 7;
        (buf ? xhB : xhA)[xh_off(kk, b)] = 0.0f;
    }
    for (int idx = tid; idx < XDIM * 8; idx += 256) {   // stage x_0
        int k = idx >> 3, b = idx & 7;
        xhA[xh_off(k, b)] = g_xseq[b * XDIM + k];
    }
    __syncthreads();

    float* cur = xhA;
    float* nxt = xhB;
    const unsigned long long ONE2 = dup2(1.0f);

    for (int s = 0; s < SQ; ++s) {
        // stage h_{s-1} (k = 364..875)
        {
            int b = tid & 7, m = tid >> 3;            // m 0..31
            const float* src = (s == 0) ? (hiddens + b * HH + m * 16)
                                        : (g_hs + (size_t)((s - 1) * 8 + b) * HH + m * 16);
            float4 v0, v1, v2, v3;
            if (s == 0) {
                v0 = *(const float4*)(src);      v1 = *(const float4*)(src + 4);
                v2 = *(const float4*)(src + 8);  v3 = *(const float4*)(src + 12);
            } else {
                v0 = __ldcg((const float4*)(src));
                v1 = __ldcg((const float4*)(src + 4));
                v2 = __ldcg((const float4*)(src + 8));
                v3 = __ldcg((const float4*)(src + 12));
            }
            float vals[16] = {v0.x, v0.y, v0.z, v0.w, v1.x, v1.y, v1.z, v1.w,
                              v2.x, v2.y, v2.z, v2.w, v3.x, v3.y, v3.z, v3.w};
            #pragma unroll
            for (int j = 0; j < 16; ++j)
                cur[xh_off(XDIM + m * 16 + j, b)] = vals[j];
        }
        __syncthreads();

        // gate partials: rows r and r+16, k = 16i+c
        unsigned long long a0 = 0, a1 = 0, a2 = 0, a3 = 0;
        unsigned long long a4 = 0, a5 = 0, a6 = 0, a7 = 0;
        const float* base = cur + c * 4;
        #pragma unroll
        for (int i = 0; i < NI; ++i) {
            ulonglong2 x01 = *(const ulonglong2*)(base + i * 128);       // b0..3
            ulonglong2 x23 = *(const ulonglong2*)(base + i * 128 + 64);  // b4..7
            unsigned long long wwA = dup2(wA[i]);
            unsigned long long wwB = dup2(wB[i]);
            ffma2(a0, x01.x, wwA); ffma2(a1, x01.y, wwA);
            ffma2(a2, x23.x, wwA); ffma2(a3, x23.y, wwA);
            ffma2(a4, x01.x, wwB); ffma2(a5, x01.y, wwB);
            ffma2(a6, x23.x, wwB); ffma2(a7, x23.y, wwB);
        }
        #pragma unroll
        for (int mask = 1; mask < 16; mask <<= 1) {
            ffma2(a0, __shfl_xor_sync(0xFFFFFFFFu, a0, mask), ONE2);
            ffma2(a1, __shfl_xor_sync(0xFFFFFFFFu, a1, mask), ONE2);
            ffma2(a2, __shfl_xor_sync(0xFFFFFFFFu, a2, mask), ONE2);
            ffma2(a3, __shfl_xor_sync(0xFFFFFFFFu, a3, mask), ONE2);
            ffma2(a4, __shfl_xor_sync(0xFFFFFFFFu, a4, mask), ONE2);
            ffma2(a5, __shfl_xor_sync(0xFFFFFFFFu, a5, mask), ONE2);
            ffma2(a6, __shfl_xor_sync(0xFFFFFFFFu, a6, mask), ONE2);
            ffma2(a7, __shfl_xor_sync(0xFFFFFFFFu, a7, mask), ONE2);
        }
        if (c == 0) {
            unsigned long long* gs = (unsigned long long*)gate_s;
            gs[r * 4 + 0] = a0; gs[r * 4 + 1] = a1;
            gs[r * 4 + 2] = a2; gs[r * 4 + 3] = a3;
            gs[(r + 16) * 4 + 0] = a4; gs[(r + 16) * 4 + 1] = a5;
            gs[(r + 16) * 4 + 2] = a6; gs[(r + 16) * 4 + 3] = a7;
        }
        __syncthreads();

        // cell phase A: all 256 threads, one DP nonlinearity each
        {
            int grow = tid >> 3;                 // 0..31
            double val = (double)(gate_s[tid] + bias_s[grow]);
            int gg = grow >> 3;                  // gate type
            nl_s[tid] = (gg == 2) ? tanh(val) : 1.0 / (1.0 + exp(-val));
        }
        __syncthreads();
        // cell phase B: 64 threads
        if (tid < 64) {
            int j2 = tid >> 3, b = tid & 7;
            double si = nl_s[tid];
            double sf = nl_s[64 + tid];
            double tg = nl_s[128 + tid];
            double so = nl_s[192 + tid];
            double cn = sf * (double)c_s[tid] + si * tg;
            float cnf = (float)cn;
            float hnf = (float)(so * tanh((double)cnf));
            c_s[tid] = cnf;
            g_hs[(size_t)(s * 8 + b) * HH + j0 + j2] = hnf;
        }
        __syncthreads();

        if (s + 1 < SQ) {
            for (int idx = tid; idx < XDIM * 8; idx += 256) {   // stage x_{s+1}
                int k = idx >> 3, b = idx & 7;
                nxt[xh_off(k, b)] = g_xseq[(size_t)((s + 1) * 8 + b) * XDIM + k];
            }
            if (tid == 0) {   // release-arrive + acquire-spin grid barrier
                asm volatile("red.release.gpu.global.add.u32 [%0], %1;"
                             :: "l"(&g_bars[s]), "r"(1u) : "memory");
                unsigned v;
                do {
                    asm volatile("ld.acquire.gpu.global.u32 %0, [%1];"
                                 : "=r"(v) : "l"(&g_bars[s]) : "memory");
                } while (v < (unsigned)LSTM_BLOCKS);
            }
            __syncthreads();
        }
        float* tmp = cur; cur = nxt; nxt = tmp;
    }
}

// ---------------- kernel 3: fp32 f32x2 logits GEMM (conflict-free) ----------
// Thread = 4m x 4 n-pairs, n = tn*2 + j*32 + {0,1}. w loads: one u64 per lane
// at 8B stride -> 16 lanes cover 32 banks exactly (conflict-free, broadcast
// across tm halves). Same sequential-k fma order as R10/R11 -> identical logits.
#define BMX 64
#define BNX 128
#define BKX 16

__global__ __launch_bounds__(256, 2) void k_logits(const float* __restrict__ Wout,
                                                   const float* __restrict__ bout) {
    __shared__ float sA[BKX * BMX];
    __shared__ float sW[BKX * BNX];
    __shared__ unsigned long long sKey[BMX];

    const int tid = threadIdx.x;
    const int n0 = blockIdx.x * BNX;
    const int m0 = blockIdx.y * BMX;
    const int tm = tid >> 4;            // m = tm*4 + 0..3
    const int tn = tid & 15;            // n-pairs at tn*2 + j*32

    if (tid < BMX) sKey[tid] = 0ull;

    const int ar = tid >> 2;
    const int ak = (tid & 3) * 4;
    const int wr = tid >> 1;
    const int wk = (tid & 1) * 8;
    const float* gA = g_hs + (size_t)(m0 + ar) * HH + ak;
    const float* gW = Wout + (size_t)(n0 + wr) * HH + wk;

    unsigned long long acc[4][4];
    #pragma unroll
    for (int m = 0; m < 4; ++m)
        #pragma unroll
        for (int j = 0; j < 4; ++j) acc[m][j] = 0ull;

    float4 pa  = *(const float4*)gA;
    float4 pw0 = *(const float4*)gW;
    float4 pw1 = *(const float4*)(gW + 4);

    const int NT = HH / BKX;            // 32
    for (int t = 0; t < NT; ++t) {
        sA[(ak + 0) * BMX + ar] = pa.x;
        sA[(ak + 1) * BMX + ar] = pa.y;
        sA[(ak + 2) * BMX + ar] = pa.z;
        sA[(ak + 3) * BMX + ar] = pa.w;
        sW[(wk + 0) * BNX + wr] = pw0.x;
        sW[(wk + 1) * BNX + wr] = pw0.y;
        sW[(wk + 2) * BNX + wr] = pw0.z;
        sW[(wk + 3) * BNX + wr] = pw0.w;
        sW[(wk + 4) * BNX + wr] = pw1.x;
        sW[(wk + 5) * BNX + wr] = pw1.y;
        sW[(wk + 6) * BNX + wr] = pw1.z;
        sW[(wk + 7) * BNX + wr] = pw1.w;
        __syncthreads();
        if (t + 1 < NT) {
            pa  = *(const float4*)(gA + (t + 1) * BKX);
            pw0 = *(const float4*)(gW + (t + 1) * BKX);
            pw1 = *(const float4*)(gW + (t + 1) * BKX + 4);
        }
        #pragma unroll
        for (int k = 0; k < BKX; ++k) {
            float4 av = *(const float4*)(sA + k * BMX + tm * 4);
            const float* wrow = sW + k * BNX + tn * 2;
            unsigned long long w0 = *(const unsigned long long*)(wrow);
            unsigned long long w1 = *(const unsigned long long*)(wrow + 32);
            unsigned long long w2 = *(const unsigned long long*)(wrow + 64);
            unsigned long long w3 = *(const unsigned long long*)(wrow + 96);
            unsigned long long am;
            am = dup2(av.x);
            ffma2(acc[0][0], w0, am); ffma2(acc[0][1], w1, am);
            ffma2(acc[0][2], w2, am); ffma2(acc[0][3], w3, am);
            am = dup2(av.y);
            ffma2(acc[1][0], w0, am); ffma2(acc[1][1], w1, am);
            ffma2(acc[1][2], w2, am); ffma2(acc[1][3], w3, am);
            am = dup2(av.z);
            ffma2(acc[2][0], w0, am); ffma2(acc[2][1], w1, am);
            ffma2(acc[2][2], w2, am); ffma2(acc[2][3], w3, am);
            am = dup2(av.w);
            ffma2(acc[3][0], w0, am); ffma2(acc[3][1], w1, am);
            ffma2(acc[3][2], w2, am); ffma2(acc[3][3], w3, am);
        }
        __syncthreads();
    }

    // epilogue
    float bias[4][2];
    #pragma unroll
    for (int j = 0; j < 4; ++j) {
        bias[j][0] = __ldg(&bout[n0 + tn * 2 + j * 32]);
        bias[j][1] = __ldg(&bout[n0 + tn * 2 + j * 32 + 1]);
    }
    #pragma unroll
    for (int m = 0; m < 4; ++m) {
        int m_loc = tm * 4 + m;
        float* lrow = g_logits + (size_t)(m0 + m_loc) * VV + n0;
        unsigned long long best = 0ull;
        #pragma unroll
        for (int j = 0; j < 4; ++j) {
            float2 f = unpack2(acc[m][j]);
            float l0 = f.x + bias[j][0];
            float l1 = f.y + bias[j][1];
            int nn = tn * 2 + j * 32;
            *(float2*)(lrow + nn) = make_float2(l0, l1);
            unsigned long long k0 = make_key(l0, n0 + nn);
            unsigned long long k1 = make_key(l1, n0 + nn + 1);
            if (k0 > best) best = k0;
            if (k1 > best) best = k1;
        }
        atomicMax(&sKey[m_loc], best);
    }
    __syncthreads();
    if (tid < BMX) atomicMax(&g_best[m0 + tid], sKey[tid]);
}

// ---------------- kernel 3b: per-row Z + candidates ----------------
__global__ __launch_bounds__(256) void k_scan() {
    const int row = blockIdx.x;
    const int tid = threadIdx.x;
    __shared__ float sSum[256];
    __shared__ int sCnt;
    if (tid == 0) sCnt = 0;
    __syncthreads();

    const float rowmax = key_to_float(g_best[row]);
    const float th = rowmax - CAND_EPS;
    const float* lrow = g_logits + (size_t)row * VV;

    float acc = 0.0f;
    for (int v = tid; v < VV; v += 256) {
        float l = lrow[v];
        acc += expf(l - rowmax);
        if (l >= th) {
            int idx = atomicAdd(&sCnt, 1);
            if (idx < CAND_MAX) g_candv[row * CAND_MAX + idx] = v;
        }
    }
    sSum[tid] = acc;
    __syncthreads();
    for (int st = 128; st > 0; st >>= 1) {
        if (tid < st) sSum[tid] += sSum[tid + st];
        __syncthreads();
    }
    if (tid == 0) {
        g_Z[row] = sSum[0];
        g_candn[row] = (sCnt < CAND_MAX) ? sCnt : CAND_MAX;
    }
}

// ---------------- kernel 3c: fp64 rescore + quantized-softmax argmax ---------
__global__ __launch_bounds__(256) void k_rescore(const float* __restrict__ Wout,
                                                 const float* __restrict__ bout) {
    const int row = blockIdx.x;
    const int tid = threadIdx.x;
    const int warp = tid >> 5, lane = tid & 31;
    __shared__ double sL[CAND_MAX];

    const int n = g_candn[row];
    const float* hrow = g_hs + (size_t)row * HH;

    for (int ci = warp; ci < n; ci += 8) {
        int v = g_candv[row * CAND_MAX + ci];
        const float* wrow = Wout + (size_t)v * HH;
        double d = 0.0;
        #pragma unroll
        for (int k = lane; k < HH; k += 32)
            d += (double)hrow[k] * (double)wrow[k];
        #pragma unroll
        for (int off = 16; off > 0; off >>= 1)
            d += __shfl_down_sync(0xFFFFFFFFu, d, off);
        if (lane == 0) sL[ci] = d + (double)bout[v];
    }
    __syncthreads();

    if (tid == 0) {
        if (n <= 1) {
            g_vstar[row] = (n == 1) ? g_candv[row * CAND_MAX]
                                    : (int)(0xFFFFFFFFu - (unsigned)(g_best[row] & 0xFFFFFFFFull));
        } else {
            double M = sL[0];
            for (int i = 1; i < n; ++i) if (sL[i] > M) M = sL[i];
            float Z = g_Z[row];
            float bestp = -1.0f;
            int bestv = 0x7FFFFFFF;
            for (int i = 0; i < n; ++i) {
                float e = (float)exp(sL[i] - M);
                float p = __fdiv_rn(e, Z);
                int v = g_candv[row * CAND_MAX + i];
                if (p > bestp || (p == bestp && v < bestv)) { bestp = p; bestv = v; }
            }
            g_vstar[row] = bestv;
        }
    }
}

// ---------------- kernel 4: gather ----------------
__global__ void k_gather(const float* __restrict__ transfer, float* __restrict__ out) {
    int row = blockIdx.x;
    int vstar = g_vstar[row];
    const float* src = transfer + (size_t)vstar * EE;
    float* dst = out + (size_t)row * EE;
    for (int e = threadIdx.x; e < EE; e += blockDim.x) dst[e] = src[e];
}

// ---------------- launch ----------------
extern "C" void kernel_launch(void* const* d_in, const int* in_sizes, int n_in,
                              void* d_out, int out_size) {
    const int*   tokens    = (const int*)d_in[0];
    const int*   relations = (const int*)d_in[1];
    const float* hiddens   = (const float*)d_in[2];
    const float* embed     = (const float*)d_in[3];
    const float* transfer  = (const float*)d_in[4];
    const float* rel_emb   = (const float*)d_in[5];
    const float* W_ih      = (const float*)d_in[6];
    const float* W_hh      = (const float*)d_in[7];
    const float* b_ih      = (const float*)d_in[8];
    const float* b_hh      = (const float*)d_in[9];
    const float* W_out     = (const float*)d_in[10];
    const float* b_out     = (const float*)d_in[11];
    float* out = (float*)d_out;

    k_zero<<<8, 256>>>();
    k_xseq<<<MM, 384>>>(tokens, relations, embed, rel_emb);

    size_t smem = (size_t)(2 * XH2_FLOATS + 256 + 64 + 32) * sizeof(float)
                + 256 * sizeof(double);
    cudaFuncSetAttribute(k_lstm, cudaFuncAttributeMaxDynamicSharedMemorySize, (int)smem);
    k_lstm<<<LSTM_BLOCKS, 256, smem>>>(hiddens, W_ih, W_hh, b_ih, b_hh);

    k_logits<<<dim3(VV / BNX, MM / BMX), 256>>>(W_out, b_out);
    k_scan<<<MM, 256>>>();
    k_rescore<<<MM, 256>>>(W_out, b_out);
    k_gather<<<MM, 128>>>(transfer, out);
}